// round 15
// baseline (speedup 1.0000x reference)
#include <cuda_runtime.h>
#include <cuda_fp16.h>
#include <cstdint>

typedef __half h16;
#define NOUT 4928

// ---------------- scratch (device globals; sizes in elements) ----------------
__device__ __align__(16) h16 g_Xs5[(size_t)2048 * 2048];     // res5 fp16 [pos][2048]
__device__ __align__(16) h16 g_W1 [(size_t)512 * 18432];     // conv1 W fp16
__device__ __align__(16) h16 g_X1 [(size_t)2048 * 512];      // x1 fp16
__device__ __align__(16) h16 g_W2 [(size_t)1024 * 4608];     // conv2 W fp16 (moving 512 cin)
__device__ __align__(16) h16 g_X2 [(size_t)2048 * 1024];     // x2 fp16 (single)
__device__ __align__(16) h16 g_W3 [(size_t)4992 * 1024];     // cls1 W fp16
__device__ __align__(16) h16 g_Xr2[(size_t)131072 * 256];    // res2 fp16
__device__ __align__(16) h16 g_W4 [(size_t)64 * 2304];       // c1a W fp16
__device__ float g_gpp[8 * 16 * 512];                        // gp partials
__device__ float g_C9 [(size_t)8 * 1024 * 9];
__device__ float g_cls1T[(size_t)2048 * NOUT];               // also split-K partial buffer
__device__ float g_c1aT [(size_t)131072 * 48];

// ---------------- helpers ----------------
__device__ __forceinline__ unsigned s2u(const void* p) {
    return (unsigned)__cvta_generic_to_shared(p);
}
__device__ __forceinline__ void cpa16(unsigned d, const void* s, unsigned sz) {
    asm volatile("cp.async.ca.shared.global [%0], [%1], 16, %2;" :: "r"(d), "l"(s), "r"(sz));
}
__device__ __forceinline__ void cpa_commit() {
    asm volatile("cp.async.commit_group;" ::: "memory");
}
template<int N> __device__ __forceinline__ void cpa_wait() {
    asm volatile("cp.async.wait_group %0;" :: "n"(N) : "memory");
}
__device__ __forceinline__ void ldm4(unsigned* r, unsigned a) {
    asm volatile("ldmatrix.sync.aligned.m8n8.x4.shared.b16 {%0,%1,%2,%3}, [%4];"
        : "=r"(r[0]), "=r"(r[1]), "=r"(r[2]), "=r"(r[3]) : "r"(a));
}
__device__ __forceinline__ void mma16816(float* d, const unsigned* a, const unsigned* b) {
    asm volatile("mma.sync.aligned.m16n8k16.row.col.f32.f16.f16.f32 "
        "{%0,%1,%2,%3}, {%4,%5,%6,%7}, {%8,%9}, {%0,%1,%2,%3};"
        : "+f"(d[0]), "+f"(d[1]), "+f"(d[2]), "+f"(d[3])
        : "r"(a[0]), "r"(a[1]), "r"(a[2]), "r"(a[3]), "r"(b[0]), "r"(b[1]));
}
// swizzled smem offset: row stride 128B, 16B column XORed with row&7
__device__ __forceinline__ unsigned swz(int row, int col16) {
    return (unsigned)(row * 128 + ((col16 ^ (row & 7)) << 4));
}

// =====================================================================
// HMMA fp16 GEMM: BK=64, 3-stage pipeline, swizzled 128B rows,
// 3 CTAs/SM target (small warp tiles, <=84 regs).
// epi: 1 = +bias -> fp32 (guarded); 2 = BN+ReLU -> fp32 (guarded);
//      4 = raw fp32 split-K partial at [blockIdx.z][M][ofc]
// =====================================================================
template<int BM, int BN, int WS, bool CONV3>
__global__ __launch_bounds__(256, 3) void gemm_mma(
    const h16* __restrict__ A, const h16* __restrict__ B,
    int C3, int imh, int imw, int nk, int Kb,
    int epi, int nvalid,
    const float* __restrict__ scale, const float* __restrict__ shift,
    const float* __restrict__ bias,
    float* __restrict__ Of, int ofc)
{
    constexpr int WM = BM / (8 / WS), WN = BN / WS;
    constexpr int MT = WM / 16;
    constexpr int NT = WN / 8;
    constexpr int NF = WN / 16;
    constexpr int AJ = BM / 32;
    constexpr int BJ = (BN * 8 + 255) / 256;
    constexpr int ABYTES = BM * 128, STG = (BM + BN) * 128;

    extern __shared__ __align__(16) char sm[];
    const int tid = threadIdx.x;
    const int nb = blockIdx.x, mtile = blockIdx.y;
    const int kzoff = blockIdx.z * nk;
    const int warp = tid >> 5, lane = tid & 31;
    const int m0 = (warp / WS) * WM, n0 = (warp % WS) * WN;
    const unsigned sbase = s2u(sm);
    const int imgpix = imh * imw;
    const int vec = tid & 7;

    int arow[AJ], ay[AJ], ax[AJ], apb[AJ];
#pragma unroll
    for (int j = 0; j < AJ; j++) {
        arow[j] = (tid >> 3) + j * 32;
        int g = mtile * BM + arow[j];
        if (CONV3) {
            int bb = g / imgpix, lp = g - bb * imgpix;
            ay[j] = lp / imw; ax[j] = lp - ay[j] * imw; apb[j] = bb * imgpix;
        } else { ay[j] = 0; ax[j] = 0; apb[j] = g; }
    }

    auto load_chunk = [&](int kc, int st) {
        unsigned Ab = sbase + st * STG;
        unsigned Bb = Ab + ABYTES;
        int k0 = (kzoff + kc) * 64;
        int dy = 0, dx = 0, cb = k0;
        if (CONV3) {
            int rk = k0 / C3; cb = k0 - rk * C3;
            int r3 = rk / 3; dy = r3 - 1; dx = rk - r3 * 3 - 1;
        }
#pragma unroll
        for (int j = 0; j < AJ; j++) {
            const h16* src;
            unsigned sz = 16;
            if (CONV3) {
                int y2 = ay[j] + dy, x2 = ax[j] + dx;
                bool v = ((unsigned)y2 < (unsigned)imh) && ((unsigned)x2 < (unsigned)imw);
                src = A + (size_t)(apb[j] + y2 * imw + x2) * C3 + cb + vec * 8;
                if (!v) { src = A; sz = 0; }
            } else {
                src = A + (size_t)apb[j] * C3 + k0 + vec * 8;
            }
            cpa16(Ab + swz(arow[j], vec), src, sz);
        }
#pragma unroll
        for (int j = 0; j < BJ; j++) {
            int item = tid + 256 * j;
            int row = item >> 3;
            if ((BN * 8 % 256 == 0) || item < BN * 8)
                cpa16(Bb + swz(row, item & 7),
                      B + (size_t)(nb * BN + row) * Kb + k0 + (item & 7) * 8, 16);
        }
    };

    float acc[MT][NT][4];
#pragma unroll
    for (int a = 0; a < MT; a++)
#pragma unroll
        for (int b2 = 0; b2 < NT; b2++)
#pragma unroll
            for (int c = 0; c < 4; c++) acc[a][b2][c] = 0.f;

    auto compute = [&](int st) {
        unsigned Ab = sbase + st * STG;
        unsigned Bb = Ab + ABYTES;
#pragma unroll
        for (int step = 0; step < 4; step++) {
            unsigned af[MT][4], bfr[NF][4];
            {
                int ch = step * 2 + (lane >> 4);
#pragma unroll
                for (int i = 0; i < MT; i++) {
                    int r = m0 + 16 * i + (lane & 15);
                    ldm4(af[i], Ab + swz(r, ch));
                }
            }
            {
                int rr = (lane & 7) + ((lane >> 4) << 3);
                int ch = step * 2 + ((lane >> 3) & 1);
#pragma unroll
                for (int i = 0; i < NF; i++) {
                    int r = n0 + 16 * i + rr;
                    ldm4(bfr[i], Bb + swz(r, ch));
                }
            }
#pragma unroll
            for (int mt = 0; mt < MT; mt++)
#pragma unroll
                for (int nt = 0; nt < NT; nt++)
                    mma16816(acc[mt][nt], af[mt], &bfr[nt >> 1][(nt & 1) * 2]);
        }
    };

    load_chunk(0, 0);
    cpa_commit();
    if (nk > 1) load_chunk(1, 1);
    cpa_commit();
    int st2 = 2;
    for (int kc = 0; kc < nk; kc++) {
        cpa_wait<1>();
        __syncthreads();
        if (kc + 2 < nk) {
            load_chunk(kc + 2, st2);
            if (++st2 == 3) st2 = 0;
        }
        cpa_commit();
        compute(kc % 3);
    }

    // ---- epilogue ----
    float* dstz = Of;
    if (epi == 4)
        dstz = Of + (size_t)blockIdx.z * ((size_t)gridDim.y * BM) * ofc;
#pragma unroll
    for (int mt = 0; mt < MT; mt++)
#pragma unroll
        for (int nt = 0; nt < NT; nt++) {
            float* d = acc[mt][nt];
            int row = mtile * BM + m0 + mt * 16 + (lane >> 2);
            int col = nb * BN + n0 + nt * 8 + (lane & 3) * 2;
#pragma unroll
            for (int h = 0; h < 2; h++) {
                int r = row + h * 8;
                float v0 = d[h * 2 + 0], v1 = d[h * 2 + 1];
                if (epi == 4) {
                    *(float2*)(dstz + (size_t)r * ofc + col) = make_float2(v0, v1);
                } else if (epi == 1) {
                    if (col < nvalid) {
                        float2 o = make_float2(v0 + bias[col], v1 + bias[col + 1]);
                        *(float2*)(Of + (size_t)r * ofc + col) = o;
                    }
                } else {
                    if (col < nvalid) {
                        float2 o;
                        o.x = fmaxf(fmaf(v0, scale[col], shift[col]), 0.f);
                        o.y = fmaxf(fmaf(v1, scale[col + 1], shift[col + 1]), 0.f);
                        *(float2*)(Of + (size_t)r * ofc + col) = o;
                    }
                }
            }
        }
}

// ---------------- reduce split-K partials + (opt C9) + BN/ReLU -> fp16 ----------------
__global__ __launch_bounds__(256) void reduce_aug(
    const float* __restrict__ P, int ns, int M, int C,
    const float* __restrict__ corr,
    const float* __restrict__ scale, const float* __restrict__ shift,
    h16* __restrict__ out)
{
    int idx = (blockIdx.x * 256 + threadIdx.x) * 4;
    int r = idx / C, col = idx - r * C;
    if (r >= M) return;
    float4 v = *(const float4*)(P + (size_t)r * C + col);
    for (int s = 1; s < ns; s++) {
        float4 p = *(const float4*)(P + ((size_t)s * M + r) * C + col);
        v.x += p.x; v.y += p.y; v.z += p.z; v.w += p.w;
    }
    if (corr) {
        int lp = r & 255, y = lp >> 4, xp = lp & 15;
        int cls = ((y == 0) ? 0 : ((y == 15) ? 6 : 3))
                + ((xp == 0) ? 0 : ((xp == 15) ? 2 : 1));
        const float* cp = corr + (size_t)(r >> 8) * 1024 * 9 + (size_t)col * 9 + cls;
        v.x += cp[0]; v.y += cp[9]; v.z += cp[18]; v.w += cp[27];
    }
    float4 sc = *(const float4*)(scale + col);
    float4 sh = *(const float4*)(shift + col);
    v.x = fmaxf(fmaf(v.x, sc.x, sh.x), 0.f);
    v.y = fmaxf(fmaf(v.y, sc.y, sh.y), 0.f);
    v.z = fmaxf(fmaf(v.z, sc.z, sh.z), 0.f);
    v.w = fmaxf(fmaf(v.w, sc.w, sh.w), 0.f);
    ushort4 u;
    u.x = __half_as_ushort(__float2half_rn(v.x));
    u.y = __half_as_ushort(__float2half_rn(v.y));
    u.z = __half_as_ushort(__float2half_rn(v.z));
    u.w = __half_as_ushort(__float2half_rn(v.w));
    *(ushort4*)(out + (size_t)r * C + col) = u;
}

// =====================================================================
// Unified prep (unchanged from round 14).
// =====================================================================
__global__ __launch_bounds__(256) void prep_all(
    const float* __restrict__ res5, const float* __restrict__ res2,
    const float* __restrict__ bw,   const float* __restrict__ c0w,
    const float* __restrict__ aw,   const float* __restrict__ c1w,
    h16* __restrict__ Xs5, h16* __restrict__ Xr2,
    h16* __restrict__ W1,  h16* __restrict__ W2,
    h16* __restrict__ W4,  h16* __restrict__ W3)
{
    __shared__ float tt[64][33];
    __shared__ float tw[9][132];
    const int blk = blockIdx.x, tid = threadIdx.x;

    if (blk < 18432) {
        const float* in; h16* out; int C, HW, b, c0, p0;
        if (blk < 2048) {
            in = res5; out = Xs5; C = 2048; HW = 256;
            p0 = (blk & 7) * 32; c0 = ((blk >> 3) & 31) * 64; b = blk >> 8;
        } else {
            int l = blk - 2048;
            in = res2; out = Xr2; C = 256; HW = 16384;
            p0 = (l & 511) * 32; c0 = ((l >> 9) & 3) * 64; b = l >> 11;
        }
        {
            const int tx = tid & 31, ty = tid >> 5;
#pragma unroll
            for (int r = 0; r < 8; r++)
                tt[ty + 8 * r][tx] = in[((size_t)b * C + c0 + ty + 8 * r) * HW + p0 + tx];
        }
        __syncthreads();
        {
            const int cc = tid & 63, pq = tid >> 6;
#pragma unroll
            for (int r = 0; r < 8; r++) {
                int p = pq + 4 * r;
                out[((size_t)b * HW + p0 + p) * C + c0 + cc] =
                    __float2half_rn(tt[cc][p]);
            }
        }
    } else if (blk < 19968) {
        const float* wsrc; h16* wdst; int C, CI, ntile, oc;
        if (blk < 18944) { oc = blk - 18432; wsrc = bw;  wdst = W1; C = 2048; CI = 2048; ntile = 16; }
        else             { oc = blk - 18944; wsrc = c0w; wdst = W2; C = 512;  CI = 1024; ntile = 4; }
        for (int ct = 0; ct < ntile; ct++) {
            int c0 = ct * 128;
            for (int i = tid; i < 1152; i += 256) {
                int c = i / 9, tap = i - c * 9;
                tw[tap][c] = wsrc[(size_t)oc * CI * 9 + (size_t)(c0 + c) * 9 + tap];
            }
            __syncthreads();
            for (int i = tid; i < 1152; i += 256) {
                int tap = i >> 7, c = i & 127;
                wdst[(size_t)oc * 9 * C + (size_t)tap * C + c0 + c] =
                    __float2half_rn(tw[tap][c]);
            }
            __syncthreads();
        }
    } else {
        const int N4 = 64 * 9 * 256;
        int idx = (blk - 19968) * 256 + tid;
        if (idx < N4) {
            int oc = idx / (9 * 256); int rem = idx - oc * 9 * 256;
            int tap = rem / 256; int c = rem - tap * 256;
            float v = (oc < 48) ? aw[((size_t)oc * 256 + c) * 9 + tap] : 0.f;
            W4[(size_t)oc * 2304 + (size_t)tap * 256 + c] = __float2half_rn(v);
        } else {
            int i2 = idx - N4;
            if (i2 < 4992 * 1024) {
                int oc = i2 >> 10;
                float v = (oc < NOUT) ? c1w[i2] : 0.f;
                W3[i2] = __float2half_rn(v);
            }
        }
    }
}

// ---------------- gp partials ----------------
__global__ __launch_bounds__(512) void gp_part(
    const h16* __restrict__ X1, float* __restrict__ gpp)
{
    const int b = blockIdx.x, pg = blockIdx.y, c = threadIdx.x;
    float s = 0.f;
#pragma unroll
    for (int i = 0; i < 16; i++) {
        int p = pg * 16 + i;
        s += __half2float(X1[((size_t)(b * 256 + p)) * 512 + c]);
    }
    gpp[((size_t)(b * 16 + pg)) * 512 + c] = s;
}

// ---------------- C9 ----------------
__global__ __launch_bounds__(128) void c9_kernel(
    const float* __restrict__ w, const float* __restrict__ gpp, float* __restrict__ C9)
{
    __shared__ float sgp[512];
    __shared__ float sT[16][9];
    const int b = blockIdx.y, oc0 = blockIdx.x * 16, tid = threadIdx.x;
    for (int i = tid; i < 512; i += 128) {
        float s = 0.f;
#pragma unroll
        for (int pg = 0; pg < 16; pg++)
            s += gpp[((size_t)(b * 16 + pg)) * 512 + i];
        sgp[i] = s * (1.f / 256.f);
    }
    __syncthreads();

    const int oc = oc0 + (tid >> 3), ln = tid & 7;
    float t[9];
#pragma unroll
    for (int k = 0; k < 9; k++) t[k] = 0.f;
    for (int c = ln * 64; c < ln * 64 + 64; c++) {
        float g = sgp[c];
        const float* wp = w + ((size_t)oc * 1024 + 512 + c) * 9;
#pragma unroll
        for (int k = 0; k < 9; k++) t[k] = fmaf(wp[k], g, t[k]);
    }
#pragma unroll
    for (int o = 4; o; o >>= 1)
#pragma unroll
        for (int k = 0; k < 9; k++) t[k] += __shfl_down_sync(0xffffffffu, t[k], o, 8);
    if (ln == 0)
#pragma unroll
        for (int k = 0; k < 9; k++) sT[tid >> 3][k] = t[k];
    __syncthreads();

    for (int i = tid; i < 144; i += 128) {
        int o = i / 9, cls = i - (i / 9) * 9;
        int fy = cls / 3, fx = cls - fy * 3;
        float s = 0.f;
#pragma unroll
        for (int ky = 0; ky < 3; ky++) {
            if ((fy == 0 && ky == 0) || (fy == 2 && ky == 2)) continue;
#pragma unroll
            for (int kx = 0; kx < 3; kx++) {
                if ((fx == 0 && kx == 0) || (fx == 2 && kx == 2)) continue;
                s += sT[o][ky * 3 + kx];
            }
        }
        C9[((size_t)b * 1024 + oc0 + o) * 9 + cls] = s;
    }
}

// =====================================================================
// fused tail (unchanged from round 14)
// =====================================================================
__global__ __launch_bounds__(256) void fused_final(
    const float* __restrict__ cls1T, const float* __restrict__ c1aT,
    const float* __restrict__ c1b_w, const float* __restrict__ c1b_b,
    const float* __restrict__ cat_scale, const float* __restrict__ cat_shift,
    float* __restrict__ out)
{
    extern __shared__ __align__(16) char fsm[];
    float* sP  = (float*)fsm;
    float* sWb = (float*)(fsm + 19712);
    char*  U   = fsm + 19712 + 3136;
    float* sAc = (float*)U;
    float* sI  = (float*)(U + 12288);
    float* sH0 = (float*)(U + 16896);
    float* sH1 = (float*)(U + 20992);
    char*  sAw = U;
    char*  sB  = U + 25088;

    const int b = blockIdx.y, lpos = blockIdx.x;
    const int ly = lpos >> 4, lx = lpos & 15;
    const int tid = threadIdx.x;
    const int px = tid & 63, q = tid >> 6;
    const int py = px >> 3, pxx = px & 7;
    const int lane = tid & 31;

    const float* pp = cls1T + (size_t)(b * 256 + lpos) * NOUT;
    for (int i = tid; i < NOUT; i += 256) sP[i] = pp[i];
    for (int i = tid; i < 48 * 64; i += 256) {
        int p = i / 48, ch = i - p * 48;
        int yy = ly * 8 + (p >> 3), xx = lx * 8 + (p & 7);
        sAc[ch * 64 + p] = c1aT[((size_t)b * 16384 + yy * 128 + xx) * 48 + ch];
    }
    for (int i = tid; i < 768; i += 256) sWb[i] = c1b_w[i];
    if (tid < 16) sWb[768 + tid] = c1b_b[tid];
    __syncthreads();

#pragma unroll
    for (int jj = 0; jj < 4; jj++) {
        int j = q * 4 + jj;
        float s = sWb[768 + j];
#pragma unroll
        for (int c = 0; c < 48; c++)
            s = fmaf(sAc[c * 64 + px], sWb[j * 48 + c], s);
        sI[(2 + j) * 64 + px] = fmaf(s, cat_scale[2 + j], cat_shift[2 + j]);
    }
    if (q == 0) {
        sI[px]      = fmaf((float)pxx * 0.125f, cat_scale[0], cat_shift[0]);
        sI[64 + px] = fmaf((float)py  * 0.125f, cat_scale[1], cat_shift[1]);
    }
    __syncthreads();

#pragma unroll
    for (int jj = 0; jj < 4; jj++) {
        int o = q * 4 + jj;
        float s = sP[288 + o];
#pragma unroll
        for (int c = 0; c < 18; c++)
            s = fmaf(sP[o * 18 + c], sI[c * 64 + px], s);
        sH0[o * 64 + px] = fmaxf(s, 0.f);
    }
    __syncthreads();

#pragma unroll
    for (int jj = 0; jj < 4; jj++) {
        int o = q * 4 + jj;
        float s = sP[560 + o];
#pragma unroll
        for (int c = 0; c < 16; c++)
            s = fmaf(sP[304 + o * 16 + c], sH0[c * 64 + px], s);
        sH1[o * 64 + px] = fmaxf(s, 0.f);
    }
    __syncthreads();

    for (int t = tid; t < 1024; t += 256) {
        int p2 = t & 63, c = t >> 6;
        h16 hh = __float2half_rn(sH1[c * 64 + p2]);
        *(h16*)(sB + p2 * 80 + c * 2) = hh;
        *(h16*)(sB + p2 * 80 + 32 + c * 2) = hh;
    }
    for (int t = tid; t < 4096; t += 256) {
        int o = t >> 4, c = t & 15;
        float w = sP[576 + t];
        h16 wh = __float2half_rn(w);
        h16 wl = __float2half_rn(w - __half2float(wh));
        *(h16*)(sAw + o * 80 + c * 2) = wh;
        *(h16*)(sAw + o * 80 + 32 + c * 2) = wl;
    }
    __syncthreads();

    const int warp = tid >> 5;
    const int m0 = warp * 32;
    const unsigned sAb = s2u(sAw), sBb = s2u(sB);
    float acc[2][8][4];
#pragma unroll
    for (int a = 0; a < 2; a++)
#pragma unroll
        for (int n2 = 0; n2 < 8; n2++)
#pragma unroll
            for (int c = 0; c < 4; c++) acc[a][n2][c] = 0.f;

#pragma unroll
    for (int step = 0; step < 2; step++) {
        unsigned af[2][4], bfr[4][4];
        int ch = step * 2 + (lane >> 4);
#pragma unroll
        for (int i = 0; i < 2; i++)
            ldm4(af[i], sAb + (m0 + 16 * i + (lane & 15)) * 80 + ch * 16);
        int rr = (lane & 7) + ((lane >> 4) << 3);
        int chB = step * 2 + ((lane >> 3) & 1);
#pragma unroll
        for (int i = 0; i < 4; i++)
            ldm4(bfr[i], sBb + (16 * i + rr) * 80 + chB * 16);
#pragma unroll
        for (int mt = 0; mt < 2; mt++)
#pragma unroll
            for (int nt = 0; nt < 8; nt++)
                mma16816(acc[mt][nt], af[mt], &bfr[nt >> 1][(nt & 1) * 2]);
    }

    float* obase = out + ((size_t)b << 22) + (ly * 8) * 128 + lx * 8;
#pragma unroll
    for (int mt = 0; mt < 2; mt++)
#pragma unroll
        for (int nt = 0; nt < 8; nt++) {
            float* d = acc[mt][nt];
            int o = m0 + mt * 16 + (lane >> 2);
            int pxx2 = (lane & 3) * 2;
#pragma unroll
            for (int h2 = 0; h2 < 2; h2++) {
                int oo = o + h2 * 8;
                float bv = sP[4672 + oo];
                float2 v = make_float2(d[h2 * 2] + bv, d[h2 * 2 + 1] + bv);
                *(float2*)(obase + ((size_t)oo << 14) + nt * 128 + pxx2) = v;
            }
        }
}

// ---------------- host launcher ----------------
extern "C" void kernel_launch(void* const* d_in, const int* in_sizes, int n_in,
                              void* d_out, int out_size)
{
    const float* res5 = (const float*)d_in[0];
    const float* res2 = (const float*)d_in[1];
    const float* bw   = (const float*)d_in[2];
    const float* bn1s = (const float*)d_in[3];
    const float* bn1h = (const float*)d_in[4];
    const float* c0w  = (const float*)d_in[5];
    const float* bn2s = (const float*)d_in[6];
    const float* bn2h = (const float*)d_in[7];
    const float* c1w  = (const float*)d_in[8];
    const float* c1b  = (const float*)d_in[9];
    const float* aw   = (const float*)d_in[10];
    const float* bn3s = (const float*)d_in[11];
    const float* bn3h = (const float*)d_in[12];
    const float* bw2  = (const float*)d_in[13];
    const float* bb2  = (const float*)d_in[14];
    const float* cats = (const float*)d_in[15];
    const float* cath = (const float*)d_in[16];
    float* out = (float*)d_out;

    h16 *Xs5, *W1, *X1, *W2, *X2, *W3, *Xr2, *W4;
    float *gpp, *C9, *cls1T, *c1aT;
    cudaGetSymbolAddress((void**)&Xs5, g_Xs5);
    cudaGetSymbolAddress((void**)&W1,  g_W1);
    cudaGetSymbolAddress((void**)&X1,  g_X1);
    cudaGetSymbolAddress((void**)&W2,  g_W2);
    cudaGetSymbolAddress((void**)&X2,  g_X2);
    cudaGetSymbolAddress((void**)&W3,  g_W3);
    cudaGetSymbolAddress((void**)&Xr2, g_Xr2);
    cudaGetSymbolAddress((void**)&W4,  g_W4);
    cudaGetSymbolAddress((void**)&gpp, g_gpp);
    cudaGetSymbolAddress((void**)&C9,  g_C9);
    cudaGetSymbolAddress((void**)&cls1T, g_cls1T);
    cudaGetSymbolAddress((void**)&c1aT,  g_c1aT);

    const int SM_G  = (128 + 64) * 128 * 3;    // 73728
    const int SM_C4 = (128 + 48) * 128 * 3;    // 67584
    const int SM_FF = 53056;
    cudaFuncSetAttribute(gemm_mma<128, 64, 2, true>,   cudaFuncAttributeMaxDynamicSharedMemorySize, SM_G);
    cudaFuncSetAttribute(gemm_mma<128, 64, 2, false>,  cudaFuncAttributeMaxDynamicSharedMemorySize, SM_G);
    cudaFuncSetAttribute(gemm_mma<128, 48, 1, true>,   cudaFuncAttributeMaxDynamicSharedMemorySize, SM_C4);
    cudaFuncSetAttribute(fused_final,                  cudaFuncAttributeMaxDynamicSharedMemorySize, SM_FF);

    // 1) unified prep
    prep_all<<<40512, 256>>>(res5, res2, bw, c0w, aw, c1w, Xs5, Xr2, W1, W2, W4, W3);
    // 2) conv1 GEMM: K = 18432, split-K x4 -> partials
    gemm_mma<128, 64, 2, true><<<dim3(8, 16, 4), 256, SM_G>>>(
        Xs5, W1, 2048, 16, 16, 72, 18432, 4, 512,
        nullptr, nullptr, nullptr, cls1T, 512);
    // 3) reduce -> X1 fp16
    reduce_aug<<<(2048 * 512 / 4) / 256, 256>>>(cls1T, 4, 2048, 512, nullptr, bn1s, bn1h, X1);
    // 4) conv2 GEMM (profiled slot): K = 4608, split-K x2 -> partials into c1aT
    gemm_mma<128, 64, 2, true><<<dim3(16, 16, 2), 256, SM_G>>>(
        X1, W2, 512, 16, 16, 36, 4608, 4, 1024,
        nullptr, nullptr, nullptr, c1aT, 1024);
    // 5) gp partials
    gp_part<<<dim3(8, 16), 512>>>(X1, gpp);
    // 6) C9 correction table
    c9_kernel<<<dim3(64, 8), 128>>>(c0w, gpp, C9);
    // 7) reduce (+C9) -> X2 fp16
    reduce_aug<<<(2048 * 1024 / 4) / 256, 256>>>(c1aT, 2, 2048, 1024, C9, bn2s, bn2h, X2);
    // 8) cls1 GEMM: 77 x 64 = 4928 exactly, K = 1024 (16 chunks)
    gemm_mma<128, 64, 2, false><<<dim3(77, 16, 1), 256, SM_G>>>(
        X2, W3, 1024, 16, 16, 16, 1024, 1, NOUT,
        nullptr, nullptr, c1b, cls1T, NOUT);
    // 9) c1a GEMM: K = 2304 (36 chunks) -> c1aT fp32
    gemm_mma<128, 48, 1, true><<<dim3(1, 1024, 1), 256, SM_C4>>>(
        Xr2, W4, 256, 128, 128, 36, 2304, 2, 48,
        bn3s, bn3h, nullptr, c1aT, 48);
    // 10) fused tail
    fused_final<<<dim3(256, 8), 256, SM_FF>>>(cls1T, c1aT, bw2, bb2, cats, cath, out);
}

// round 16
// speedup vs baseline: 1.0774x; 1.0774x over previous
#include <cuda_runtime.h>
#include <cuda_fp16.h>
#include <cstdint>

typedef __half h16;
#define NOUT 4928

// ---------------- scratch (device globals; sizes in elements) ----------------
__device__ __align__(16) h16 g_Xs5[(size_t)2048 * 2048];     // res5 fp16 [pos][2048]
__device__ __align__(16) h16 g_W1 [(size_t)512 * 18432];     // conv1 W fp16
__device__ __align__(16) h16 g_X1 [(size_t)2048 * 512];      // x1 fp16
__device__ __align__(16) h16 g_W2 [(size_t)1024 * 4608];     // conv2 W fp16 (moving 512 cin)
__device__ __align__(16) h16 g_X2 [(size_t)2048 * 1024];     // x2 fp16 (single)
__device__ __align__(16) h16 g_W3 [(size_t)4992 * 1024];     // cls1 W fp16
__device__ __align__(16) h16 g_Xr2[(size_t)131072 * 256];    // res2 fp16
__device__ __align__(16) h16 g_W4 [(size_t)64 * 2304];       // c1a W fp16
__device__ float g_gpp[8 * 16 * 512];                        // gp partials
__device__ float g_C9 [(size_t)8 * 1024 * 9];
__device__ float g_cls1T[(size_t)2048 * NOUT];               // also split-K partial buffer
__device__ float g_c1aT [(size_t)131072 * 48];

// ---------------- helpers ----------------
__device__ __forceinline__ unsigned s2u(const void* p) {
    return (unsigned)__cvta_generic_to_shared(p);
}
__device__ __forceinline__ void cpa16(unsigned d, const void* s, unsigned sz) {
    asm volatile("cp.async.ca.shared.global [%0], [%1], 16, %2;" :: "r"(d), "l"(s), "r"(sz));
}
__device__ __forceinline__ void cpa_commit() {
    asm volatile("cp.async.commit_group;" ::: "memory");
}
template<int N> __device__ __forceinline__ void cpa_wait() {
    asm volatile("cp.async.wait_group %0;" :: "n"(N) : "memory");
}
__device__ __forceinline__ void ldm4(unsigned* r, unsigned a) {
    asm volatile("ldmatrix.sync.aligned.m8n8.x4.shared.b16 {%0,%1,%2,%3}, [%4];"
        : "=r"(r[0]), "=r"(r[1]), "=r"(r[2]), "=r"(r[3]) : "r"(a));
}
__device__ __forceinline__ void mma16816(float* d, const unsigned* a, const unsigned* b) {
    asm volatile("mma.sync.aligned.m16n8k16.row.col.f32.f16.f16.f32 "
        "{%0,%1,%2,%3}, {%4,%5,%6,%7}, {%8,%9}, {%0,%1,%2,%3};"
        : "+f"(d[0]), "+f"(d[1]), "+f"(d[2]), "+f"(d[3])
        : "r"(a[0]), "r"(a[1]), "r"(a[2]), "r"(a[3]), "r"(b[0]), "r"(b[1]));
}

// =====================================================================
// HMMA fp16 GEMM: BK=64, 3-stage cp.async pipeline, 2 CTAs/SM.
// SMEM rows 144B stride (conflict-free ldmatrix).
// epi: 1 = +bias -> fp32 (guarded); 2 = BN+ReLU -> fp32 (guarded);
//      4 = raw fp32 split-K partial at [blockIdx.z][M][ofc]
// =====================================================================
template<int BM, int BN, int WS, bool CONV3>
__global__ __launch_bounds__(256, 2) void gemm_mma(
    const h16* __restrict__ A, const h16* __restrict__ B,
    int C3, int imh, int imw, int nk, int Kb,
    int epi, int nvalid,
    const float* __restrict__ scale, const float* __restrict__ shift,
    const float* __restrict__ bias,
    float* __restrict__ Of, int ofc)
{
    constexpr int WM = BM / (8 / WS), WN = BN / WS;
    constexpr int MT = WM / 16;
    constexpr int NT = WN / 8;
    constexpr int NF = WN / 16;
    constexpr int AJ = BM / 32;
    constexpr int BJ = (BN * 8 + 255) / 256;
    constexpr int ABYTES = BM * 144, STG = (BM + BN) * 144;

    extern __shared__ __align__(16) char sm[];
    const int tid = threadIdx.x;
    const int nb = blockIdx.x, mtile = blockIdx.y;
    const int kzoff = blockIdx.z * nk;
    const int warp = tid >> 5, lane = tid & 31;
    const int m0 = (warp / WS) * WM, n0 = (warp % WS) * WN;
    const unsigned sbase = s2u(sm);
    const int imgpix = imh * imw;
    const int vec = tid & 7;

    int arow[AJ], ay[AJ], ax[AJ], apb[AJ];
#pragma unroll
    for (int j = 0; j < AJ; j++) {
        arow[j] = (tid >> 3) + j * 32;
        int g = mtile * BM + arow[j];
        if (CONV3) {
            int bb = g / imgpix, lp = g - bb * imgpix;
            ay[j] = lp / imw; ax[j] = lp - ay[j] * imw; apb[j] = bb * imgpix;
        } else { ay[j] = 0; ax[j] = 0; apb[j] = g; }
    }

    auto load_chunk = [&](int kc, int st) {
        unsigned Ab = sbase + st * STG;
        unsigned Bb = Ab + ABYTES;
        int k0 = (kzoff + kc) * 64;
        int dy = 0, dx = 0, cb = k0;
        if (CONV3) {
            int rk = k0 / C3; cb = k0 - rk * C3;
            int r3 = rk / 3; dy = r3 - 1; dx = rk - r3 * 3 - 1;
        }
#pragma unroll
        for (int j = 0; j < AJ; j++) {
            const h16* src;
            unsigned sz = 16;
            if (CONV3) {
                int y2 = ay[j] + dy, x2 = ax[j] + dx;
                bool v = ((unsigned)y2 < (unsigned)imh) && ((unsigned)x2 < (unsigned)imw);
                src = A + (size_t)(apb[j] + y2 * imw + x2) * C3 + cb + vec * 8;
                if (!v) { src = A; sz = 0; }
            } else {
                src = A + (size_t)apb[j] * C3 + k0 + vec * 8;
            }
            cpa16(Ab + arow[j] * 144 + vec * 16, src, sz);
        }
#pragma unroll
        for (int j = 0; j < BJ; j++) {
            int item = tid + 256 * j;
            int row = item >> 3;
            if ((BN * 8 % 256 == 0) || item < BN * 8)
                cpa16(Bb + row * 144 + (item & 7) * 16,
                      B + (size_t)(nb * BN + row) * Kb + k0 + (item & 7) * 8, 16);
        }
    };

    float acc[MT][NT][4];
#pragma unroll
    for (int a = 0; a < MT; a++)
#pragma unroll
        for (int b2 = 0; b2 < NT; b2++)
#pragma unroll
            for (int c = 0; c < 4; c++) acc[a][b2][c] = 0.f;

    auto compute = [&](int st) {
        unsigned Ab = sbase + st * STG;
        unsigned Bb = Ab + ABYTES;
#pragma unroll
        for (int step = 0; step < 4; step++) {
            unsigned af[MT][4], bfr[NF][4];
            {
                int ch = step * 2 + (lane >> 4);
#pragma unroll
                for (int i = 0; i < MT; i++)
                    ldm4(af[i], Ab + (m0 + 16 * i + (lane & 15)) * 144 + ch * 16);
            }
            {
                int rr = (lane & 7) + ((lane >> 4) << 3);
                int ch = step * 2 + ((lane >> 3) & 1);
#pragma unroll
                for (int i = 0; i < NF; i++)
                    ldm4(bfr[i], Bb + (n0 + 16 * i + rr) * 144 + ch * 16);
            }
#pragma unroll
            for (int mt = 0; mt < MT; mt++)
#pragma unroll
                for (int nt = 0; nt < NT; nt++)
                    mma16816(acc[mt][nt], af[mt], &bfr[nt >> 1][(nt & 1) * 2]);
        }
    };

    load_chunk(0, 0);
    cpa_commit();
    if (nk > 1) load_chunk(1, 1);
    cpa_commit();
    int st2 = 2;
    for (int kc = 0; kc < nk; kc++) {
        cpa_wait<1>();
        __syncthreads();
        if (kc + 2 < nk) {
            load_chunk(kc + 2, st2);
            if (++st2 == 3) st2 = 0;
        }
        cpa_commit();
        compute(kc % 3);
    }

    // ---- epilogue ----
    float* dstz = Of;
    if (epi == 4)
        dstz = Of + (size_t)blockIdx.z * ((size_t)gridDim.y * BM) * ofc;
#pragma unroll
    for (int mt = 0; mt < MT; mt++)
#pragma unroll
        for (int nt = 0; nt < NT; nt++) {
            float* d = acc[mt][nt];
            int row = mtile * BM + m0 + mt * 16 + (lane >> 2);
            int col = nb * BN + n0 + nt * 8 + (lane & 3) * 2;
#pragma unroll
            for (int h = 0; h < 2; h++) {
                int r = row + h * 8;
                float v0 = d[h * 2 + 0], v1 = d[h * 2 + 1];
                if (epi == 4) {
                    *(float2*)(dstz + (size_t)r * ofc + col) = make_float2(v0, v1);
                } else if (epi == 1) {
                    if (col < nvalid) {
                        float2 o = make_float2(v0 + bias[col], v1 + bias[col + 1]);
                        *(float2*)(Of + (size_t)r * ofc + col) = o;
                    }
                } else {
                    if (col < nvalid) {
                        float2 o;
                        o.x = fmaxf(fmaf(v0, scale[col], shift[col]), 0.f);
                        o.y = fmaxf(fmaf(v1, scale[col + 1], shift[col + 1]), 0.f);
                        *(float2*)(Of + (size_t)r * ofc + col) = o;
                    }
                }
            }
        }
}

// ---------------- reduce split-K partials + (opt C9) + BN/ReLU -> fp16 ----------------
__global__ __launch_bounds__(256) void reduce_aug(
    const float* __restrict__ P, int ns, int M, int C,
    const float* __restrict__ corr,
    const float* __restrict__ scale, const float* __restrict__ shift,
    h16* __restrict__ out)
{
    int idx = (blockIdx.x * 256 + threadIdx.x) * 4;
    int r = idx / C, col = idx - r * C;
    if (r >= M) return;
    float4 v = *(const float4*)(P + (size_t)r * C + col);
    for (int s = 1; s < ns; s++) {
        float4 p = *(const float4*)(P + ((size_t)s * M + r) * C + col);
        v.x += p.x; v.y += p.y; v.z += p.z; v.w += p.w;
    }
    if (corr) {
        int lp = r & 255, y = lp >> 4, xp = lp & 15;
        int cls = ((y == 0) ? 0 : ((y == 15) ? 6 : 3))
                + ((xp == 0) ? 0 : ((xp == 15) ? 2 : 1));
        const float* cp = corr + (size_t)(r >> 8) * 1024 * 9 + (size_t)col * 9 + cls;
        v.x += cp[0]; v.y += cp[9]; v.z += cp[18]; v.w += cp[27];
    }
    float4 sc = *(const float4*)(scale + col);
    float4 sh = *(const float4*)(shift + col);
    v.x = fmaxf(fmaf(v.x, sc.x, sh.x), 0.f);
    v.y = fmaxf(fmaf(v.y, sc.y, sh.y), 0.f);
    v.z = fmaxf(fmaf(v.z, sc.z, sh.z), 0.f);
    v.w = fmaxf(fmaf(v.w, sc.w, sh.w), 0.f);
    ushort4 u;
    u.x = __half_as_ushort(__float2half_rn(v.x));
    u.y = __half_as_ushort(__float2half_rn(v.y));
    u.z = __half_as_ushort(__float2half_rn(v.z));
    u.w = __half_as_ushort(__float2half_rn(v.w));
    *(ushort4*)(out + (size_t)r * C + col) = u;
}

// =====================================================================
// Unified prep (round-14 version: 64ch x 32pos tiles, coalesced weights)
// =====================================================================
__global__ __launch_bounds__(256) void prep_all(
    const float* __restrict__ res5, const float* __restrict__ res2,
    const float* __restrict__ bw,   const float* __restrict__ c0w,
    const float* __restrict__ aw,   const float* __restrict__ c1w,
    h16* __restrict__ Xs5, h16* __restrict__ Xr2,
    h16* __restrict__ W1,  h16* __restrict__ W2,
    h16* __restrict__ W4,  h16* __restrict__ W3)
{
    __shared__ float tt[64][33];
    __shared__ float tw[9][132];
    const int blk = blockIdx.x, tid = threadIdx.x;

    if (blk < 18432) {
        const float* in; h16* out; int C, HW, b, c0, p0;
        if (blk < 2048) {
            in = res5; out = Xs5; C = 2048; HW = 256;
            p0 = (blk & 7) * 32; c0 = ((blk >> 3) & 31) * 64; b = blk >> 8;
        } else {
            int l = blk - 2048;
            in = res2; out = Xr2; C = 256; HW = 16384;
            p0 = (l & 511) * 32; c0 = ((l >> 9) & 3) * 64; b = l >> 11;
        }
        {
            const int tx = tid & 31, ty = tid >> 5;
#pragma unroll
            for (int r = 0; r < 8; r++)
                tt[ty + 8 * r][tx] = in[((size_t)b * C + c0 + ty + 8 * r) * HW + p0 + tx];
        }
        __syncthreads();
        {
            const int cc = tid & 63, pq = tid >> 6;
#pragma unroll
            for (int r = 0; r < 8; r++) {
                int p = pq + 4 * r;
                out[((size_t)b * HW + p0 + p) * C + c0 + cc] =
                    __float2half_rn(tt[cc][p]);
            }
        }
    } else if (blk < 19968) {
        const float* wsrc; h16* wdst; int C, CI, ntile, oc;
        if (blk < 18944) { oc = blk - 18432; wsrc = bw;  wdst = W1; C = 2048; CI = 2048; ntile = 16; }
        else             { oc = blk - 18944; wsrc = c0w; wdst = W2; C = 512;  CI = 1024; ntile = 4; }
        for (int ct = 0; ct < ntile; ct++) {
            int c0 = ct * 128;
            for (int i = tid; i < 1152; i += 256) {
                int c = i / 9, tap = i - c * 9;
                tw[tap][c] = wsrc[(size_t)oc * CI * 9 + (size_t)(c0 + c) * 9 + tap];
            }
            __syncthreads();
            for (int i = tid; i < 1152; i += 256) {
                int tap = i >> 7, c = i & 127;
                wdst[(size_t)oc * 9 * C + (size_t)tap * C + c0 + c] =
                    __float2half_rn(tw[tap][c]);
            }
            __syncthreads();
        }
    } else {
        const int N4 = 64 * 9 * 256;
        int idx = (blk - 19968) * 256 + tid;
        if (idx < N4) {
            int oc = idx / (9 * 256); int rem = idx - oc * 9 * 256;
            int tap = rem / 256; int c = rem - tap * 256;
            float v = (oc < 48) ? aw[((size_t)oc * 256 + c) * 9 + tap] : 0.f;
            W4[(size_t)oc * 2304 + (size_t)tap * 256 + c] = __float2half_rn(v);
        } else {
            int i2 = idx - N4;
            if (i2 < 4992 * 1024) {
                int oc = i2 >> 10;
                float v = (oc < NOUT) ? c1w[i2] : 0.f;
                W3[i2] = __float2half_rn(v);
            }
        }
    }
}

// ---------------- gp partials ----------------
__global__ __launch_bounds__(512) void gp_part(
    const h16* __restrict__ X1, float* __restrict__ gpp)
{
    const int b = blockIdx.x, pg = blockIdx.y, c = threadIdx.x;
    float s = 0.f;
#pragma unroll
    for (int i = 0; i < 16; i++) {
        int p = pg * 16 + i;
        s += __half2float(X1[((size_t)(b * 256 + p)) * 512 + c]);
    }
    gpp[((size_t)(b * 16 + pg)) * 512 + c] = s;
}

// ---------------- C9: fold gp partials + per-(b, oc, class) correction ----------------
__global__ __launch_bounds__(128) void c9_kernel(
    const float* __restrict__ w, const float* __restrict__ gpp, float* __restrict__ C9)
{
    __shared__ float sgp[512];
    __shared__ float sT[16][9];
    const int b = blockIdx.y, oc0 = blockIdx.x * 16, tid = threadIdx.x;
    for (int i = tid; i < 512; i += 128) {
        float s = 0.f;
#pragma unroll
        for (int pg = 0; pg < 16; pg++)
            s += gpp[((size_t)(b * 16 + pg)) * 512 + i];
        sgp[i] = s * (1.f / 256.f);
    }
    __syncthreads();

    const int oc = oc0 + (tid >> 3), ln = tid & 7;
    float t[9];
#pragma unroll
    for (int k = 0; k < 9; k++) t[k] = 0.f;
    for (int c = ln * 64; c < ln * 64 + 64; c++) {
        float g = sgp[c];
        const float* wp = w + ((size_t)oc * 1024 + 512 + c) * 9;
#pragma unroll
        for (int k = 0; k < 9; k++) t[k] = fmaf(wp[k], g, t[k]);
    }
#pragma unroll
    for (int o = 4; o; o >>= 1)
#pragma unroll
        for (int k = 0; k < 9; k++) t[k] += __shfl_down_sync(0xffffffffu, t[k], o, 8);
    if (ln == 0)
#pragma unroll
        for (int k = 0; k < 9; k++) sT[tid >> 3][k] = t[k];
    __syncthreads();

    for (int i = tid; i < 144; i += 128) {
        int o = i / 9, cls = i - (i / 9) * 9;
        int fy = cls / 3, fx = cls - fy * 3;
        float s = 0.f;
#pragma unroll
        for (int ky = 0; ky < 3; ky++) {
            if ((fy == 0 && ky == 0) || (fy == 2 && ky == 2)) continue;
#pragma unroll
            for (int kx = 0; kx < 3; kx++) {
                if ((fx == 0 && kx == 0) || (fx == 2 && kx == 2)) continue;
                s += sT[o][ky * 3 + kx];
            }
        }
        C9[((size_t)b * 1024 + oc0 + o) * 9 + cls] = s;
    }
}

// =====================================================================
// fused tail (round-14 version)
// =====================================================================
__global__ __launch_bounds__(256) void fused_final(
    const float* __restrict__ cls1T, const float* __restrict__ c1aT,
    const float* __restrict__ c1b_w, const float* __restrict__ c1b_b,
    const float* __restrict__ cat_scale, const float* __restrict__ cat_shift,
    float* __restrict__ out)
{
    extern __shared__ __align__(16) char fsm[];
    float* sP  = (float*)fsm;
    float* sWb = (float*)(fsm + 19712);
    char*  U   = fsm + 19712 + 3136;
    float* sAc = (float*)U;
    float* sI  = (float*)(U + 12288);
    float* sH0 = (float*)(U + 16896);
    float* sH1 = (float*)(U + 20992);
    char*  sAw = U;
    char*  sB  = U + 25088;

    const int b = blockIdx.y, lpos = blockIdx.x;
    const int ly = lpos >> 4, lx = lpos & 15;
    const int tid = threadIdx.x;
    const int px = tid & 63, q = tid >> 6;
    const int py = px >> 3, pxx = px & 7;
    const int lane = tid & 31;

    const float* pp = cls1T + (size_t)(b * 256 + lpos) * NOUT;
    for (int i = tid; i < NOUT; i += 256) sP[i] = pp[i];
    for (int i = tid; i < 48 * 64; i += 256) {
        int p = i / 48, ch = i - p * 48;
        int yy = ly * 8 + (p >> 3), xx = lx * 8 + (p & 7);
        sAc[ch * 64 + p] = c1aT[((size_t)b * 16384 + yy * 128 + xx) * 48 + ch];
    }
    for (int i = tid; i < 768; i += 256) sWb[i] = c1b_w[i];
    if (tid < 16) sWb[768 + tid] = c1b_b[tid];
    __syncthreads();

#pragma unroll
    for (int jj = 0; jj < 4; jj++) {
        int j = q * 4 + jj;
        float s = sWb[768 + j];
#pragma unroll
        for (int c = 0; c < 48; c++)
            s = fmaf(sAc[c * 64 + px], sWb[j * 48 + c], s);
        sI[(2 + j) * 64 + px] = fmaf(s, cat_scale[2 + j], cat_shift[2 + j]);
    }
    if (q == 0) {
        sI[px]      = fmaf((float)pxx * 0.125f, cat_scale[0], cat_shift[0]);
        sI[64 + px] = fmaf((float)py  * 0.125f, cat_scale[1], cat_shift[1]);
    }
    __syncthreads();

#pragma unroll
    for (int jj = 0; jj < 4; jj++) {
        int o = q * 4 + jj;
        float s = sP[288 + o];
#pragma unroll
        for (int c = 0; c < 18; c++)
            s = fmaf(sP[o * 18 + c], sI[c * 64 + px], s);
        sH0[o * 64 + px] = fmaxf(s, 0.f);
    }
    __syncthreads();

#pragma unroll
    for (int jj = 0; jj < 4; jj++) {
        int o = q * 4 + jj;
        float s = sP[560 + o];
#pragma unroll
        for (int c = 0; c < 16; c++)
            s = fmaf(sP[304 + o * 16 + c], sH0[c * 64 + px], s);
        sH1[o * 64 + px] = fmaxf(s, 0.f);
    }
    __syncthreads();

    for (int t = tid; t < 1024; t += 256) {
        int p2 = t & 63, c = t >> 6;
        h16 hh = __float2half_rn(sH1[c * 64 + p2]);
        *(h16*)(sB + p2 * 80 + c * 2) = hh;
        *(h16*)(sB + p2 * 80 + 32 + c * 2) = hh;
    }
    for (int t = tid; t < 4096; t += 256) {
        int o = t >> 4, c = t & 15;
        float w = sP[576 + t];
        h16 wh = __float2half_rn(w);
        h16 wl = __float2half_rn(w - __half2float(wh));
        *(h16*)(sAw + o * 80 + c * 2) = wh;
        *(h16*)(sAw + o * 80 + 32 + c * 2) = wl;
    }
    __syncthreads();

    const int warp = tid >> 5;
    const int m0 = warp * 32;
    const unsigned sAb = s2u(sAw), sBb = s2u(sB);
    float acc[2][8][4];
#pragma unroll
    for (int a = 0; a < 2; a++)
#pragma unroll
        for (int n2 = 0; n2 < 8; n2++)
#pragma unroll
            for (int c = 0; c < 4; c++) acc[a][n2][c] = 0.f;

#pragma unroll
    for (int step = 0; step < 2; step++) {
        unsigned af[2][4], bfr[4][4];
        int ch = step * 2 + (lane >> 4);
#pragma unroll
        for (int i = 0; i < 2; i++)
            ldm4(af[i], sAb + (m0 + 16 * i + (lane & 15)) * 80 + ch * 16);
        int rr = (lane & 7) + ((lane >> 4) << 3);
        int chB = step * 2 + ((lane >> 3) & 1);
#pragma unroll
        for (int i = 0; i < 4; i++)
            ldm4(bfr[i], sBb + (16 * i + rr) * 80 + chB * 16);
#pragma unroll
        for (int mt = 0; mt < 2; mt++)
#pragma unroll
            for (int nt = 0; nt < 8; nt++)
                mma16816(acc[mt][nt], af[mt], &bfr[nt >> 1][(nt & 1) * 2]);
    }

    float* obase = out + ((size_t)b << 22) + (ly * 8) * 128 + lx * 8;
#pragma unroll
    for (int mt = 0; mt < 2; mt++)
#pragma unroll
        for (int nt = 0; nt < 8; nt++) {
            float* d = acc[mt][nt];
            int o = m0 + mt * 16 + (lane >> 2);
            int pxx2 = (lane & 3) * 2;
#pragma unroll
            for (int h2 = 0; h2 < 2; h2++) {
                int oo = o + h2 * 8;
                float bv = sP[4672 + oo];
                float2 v = make_float2(d[h2 * 2] + bv, d[h2 * 2 + 1] + bv);
                *(float2*)(obase + ((size_t)oo << 14) + nt * 128 + pxx2) = v;
            }
        }
}

// ---------------- host launcher ----------------
extern "C" void kernel_launch(void* const* d_in, const int* in_sizes, int n_in,
                              void* d_out, int out_size)
{
    const float* res5 = (const float*)d_in[0];
    const float* res2 = (const float*)d_in[1];
    const float* bw   = (const float*)d_in[2];
    const float* bn1s = (const float*)d_in[3];
    const float* bn1h = (const float*)d_in[4];
    const float* c0w  = (const float*)d_in[5];
    const float* bn2s = (const float*)d_in[6];
    const float* bn2h = (const float*)d_in[7];
    const float* c1w  = (const float*)d_in[8];
    const float* c1b  = (const float*)d_in[9];
    const float* aw   = (const float*)d_in[10];
    const float* bn3s = (const float*)d_in[11];
    const float* bn3h = (const float*)d_in[12];
    const float* bw2  = (const float*)d_in[13];
    const float* bb2  = (const float*)d_in[14];
    const float* cats = (const float*)d_in[15];
    const float* cath = (const float*)d_in[16];
    float* out = (float*)d_out;

    h16 *Xs5, *W1, *X1, *W2, *X2, *W3, *Xr2, *W4;
    float *gpp, *C9, *cls1T, *c1aT;
    cudaGetSymbolAddress((void**)&Xs5, g_Xs5);
    cudaGetSymbolAddress((void**)&W1,  g_W1);
    cudaGetSymbolAddress((void**)&X1,  g_X1);
    cudaGetSymbolAddress((void**)&W2,  g_W2);
    cudaGetSymbolAddress((void**)&X2,  g_X2);
    cudaGetSymbolAddress((void**)&W3,  g_W3);
    cudaGetSymbolAddress((void**)&Xr2, g_Xr2);
    cudaGetSymbolAddress((void**)&W4,  g_W4);
    cudaGetSymbolAddress((void**)&gpp, g_gpp);
    cudaGetSymbolAddress((void**)&C9,  g_C9);
    cudaGetSymbolAddress((void**)&cls1T, g_cls1T);
    cudaGetSymbolAddress((void**)&c1aT,  g_c1aT);

    const int SM_BB = (128 + 128) * 144 * 3;   // 110592
    const int SM_C4 = (128 + 48) * 144 * 3;    // 76032
    const int SM_FF = 53056;
    cudaFuncSetAttribute(gemm_mma<128, 128, 2, true>,  cudaFuncAttributeMaxDynamicSharedMemorySize, SM_BB);
    cudaFuncSetAttribute(gemm_mma<128, 128, 2, false>, cudaFuncAttributeMaxDynamicSharedMemorySize, SM_BB);
    cudaFuncSetAttribute(gemm_mma<128, 48, 1, true>,   cudaFuncAttributeMaxDynamicSharedMemorySize, SM_C4);
    cudaFuncSetAttribute(fused_final,                  cudaFuncAttributeMaxDynamicSharedMemorySize, SM_FF);

    // 1) unified prep (activations + all weights)
    prep_all<<<40512, 256>>>(res5, res2, bw, c0w, aw, c1w, Xs5, Xr2, W1, W2, W4, W3);
    // 2) conv1 GEMM: BN=128 now -> grid 4x16x4 = 256 CTAs (1 wave), nk=72
    gemm_mma<128, 128, 2, true><<<dim3(4, 16, 4), 256, SM_BB>>>(
        Xs5, W1, 2048, 16, 16, 72, 18432, 4, 512,
        nullptr, nullptr, nullptr, cls1T, 512);
    // 3) reduce -> X1 fp16
    reduce_aug<<<(2048 * 512 / 4) / 256, 256>>>(cls1T, 4, 2048, 512, nullptr, bn1s, bn1h, X1);
    // 4) conv2 GEMM (profiled slot): K = 4608, split-K x2 -> partials into c1aT
    gemm_mma<128, 128, 2, true><<<dim3(8, 16, 2), 256, SM_BB>>>(
        X1, W2, 512, 16, 16, 36, 4608, 4, 1024,
        nullptr, nullptr, nullptr, c1aT, 1024);
    // 5) gp partials
    gp_part<<<dim3(8, 16), 512>>>(X1, gpp);
    // 6) C9 correction table
    c9_kernel<<<dim3(64, 8), 128>>>(c0w, gpp, C9);
    // 7) reduce (+C9) -> X2 fp16
    reduce_aug<<<(2048 * 1024 / 4) / 256, 256>>>(c1aT, 2, 2048, 1024, C9, bn2s, bn2h, X2);
    // 8) cls1 GEMM: K = 1024 (16 chunks) -> cls1T fp32
    gemm_mma<128, 128, 2, false><<<dim3(39, 16, 1), 256, SM_BB>>>(
        X2, W3, 1024, 16, 16, 16, 1024, 1, NOUT,
        nullptr, nullptr, c1b, cls1T, NOUT);
    // 9) c1a GEMM: K = 2304 (36 chunks) -> c1aT fp32
    gemm_mma<128, 48, 1, true><<<dim3(1, 1024, 1), 256, SM_C4>>>(
        Xr2, W4, 256, 128, 128, 36, 2304, 2, 48,
        bn3s, bn3h, nullptr, c1aT, 48);
    // 10) fused tail
    fused_final<<<dim3(256, 8), 256, SM_FF>>>(cls1T, c1aT, bw2, bb2, cats, cath, out);
}